// round 6
// baseline (speedup 1.0000x reference)
#include <cuda_runtime.h>
#include <cstdint>

// ChannelDropout, two-phase:
//   Phase A: scale[bc] = kept(bc) / (eps + proba(bc))   (17472 channels, ~1-2us)
//   Phase B: out[i] = sig[i] * scale[i / 750]           (pure HBM stream)
//
// Shapes: B=64, C=273, T=3000.  T/4 = 750 float4 per channel.

#define CD_TVEC   750           // float4 per channel
#define CD_NMC    100
#define CD_DROP   0.2f
#define CD_EPS    1e-8f
#define CD_VPT    8             // float4 per thread in streamer
#define CD_BLK    256
#define CD_TILE   (CD_BLK * CD_VPT)   // 2048 float4 per block

__device__ float g_scale[18432];      // >= B*C = 17472 (static scratch, no alloc)

// ---------------- Phase A: per-channel scale ----------------
__global__ __launch_bounds__(256)
void cd_scale_kernel(const float* __restrict__ pos,
                     const float* __restrict__ center,
                     const float* __restrict__ mc,
                     int BC)
{
    const int ch = blockIdx.x * blockDim.x + threadIdx.x;
    if (ch >= BC) return;

    const float px = pos[2 * ch + 0];
    const float py = pos[2 * ch + 1];

    // kept: distance from ban center (no FMA contraction -> match jax fp32)
    const float dx = px - center[0];
    const float dy = py - center[1];
    const float d2 = __fadd_rn(__fmul_rn(dx, dx), __fmul_rn(dy, dy));
    const float kept = (sqrtf(d2) > CD_DROP) ? 1.0f : 0.0f;

    int cnt = 0;
#pragma unroll 4
    for (int j = 0; j < CD_NMC; j++) {
        const float ddx = px - mc[2 * j + 0];
        const float ddy = py - mc[2 * j + 1];
        const float dd2 = __fadd_rn(__fmul_rn(ddx, ddx), __fmul_rn(ddy, ddy));
        cnt += (sqrtf(dd2) > CD_DROP) ? 1 : 0;
    }

    const float proba = (float)cnt / (float)CD_NMC;
    g_scale[ch] = kept / (CD_EPS + proba);
}

// ---------------- Phase B: flat stream ----------------
__global__ __launch_bounds__(CD_BLK)
void cd_stream_kernel(const float4* __restrict__ sig,
                      float4* __restrict__ out,
                      int total_vec)
{
    const int base = blockIdx.x * CD_TILE + threadIdx.x;

    if (base + (CD_VPT - 1) * CD_BLK < total_vec) {
        // Fast path: full tile, no predicates -> 8 batched LDG.128 up front.
        float4 v[CD_VPT];
        float  s[CD_VPT];
#pragma unroll
        for (int j = 0; j < CD_VPT; j++)
            v[j] = __ldcs(&sig[base + j * CD_BLK]);
#pragma unroll
        for (int j = 0; j < CD_VPT; j++)
            s[j] = g_scale[(unsigned)(base + j * CD_BLK) / CD_TVEC];
#pragma unroll
        for (int j = 0; j < CD_VPT; j++) {
            float4 r;
            r.x = v[j].x * s[j];
            r.y = v[j].y * s[j];
            r.z = v[j].z * s[j];
            r.w = v[j].w * s[j];
            __stcs(&out[base + j * CD_BLK], r);
        }
    } else {
        // Tail tile (one block): predicated.
#pragma unroll
        for (int j = 0; j < CD_VPT; j++) {
            const int idx = base + j * CD_BLK;
            if (idx < total_vec) {
                float4 v = __ldcs(&sig[idx]);
                const float s = g_scale[(unsigned)idx / CD_TVEC];
                float4 r;
                r.x = v.x * s;
                r.y = v.y * s;
                r.z = v.z * s;
                r.w = v.w * s;
                __stcs(&out[idx], r);
            }
        }
    }
}

extern "C" void kernel_launch(void* const* d_in, const int* in_sizes, int n_in,
                              void* d_out, int out_size)
{
    const float4* sig    = (const float4*)d_in[0];   // brain_sig  (B,C,T) fp32
    const float*  pos    = (const float*) d_in[1];   // positions  (B,C,2)
    const float*  center = (const float*) d_in[2];   // center     (2,)
    const float*  mc     = (const float*) d_in[3];   // mc_centers (100,2)
    float4*       out    = (float4*)d_out;

    const int BC        = in_sizes[1] / 2;           // 17472
    const int total_vec = in_sizes[0] / 4;           // 13,104,000

    cd_scale_kernel<<<(BC + 255) / 256, 256>>>(pos, center, mc, BC);

    const int nblocks = (total_vec + CD_TILE - 1) / CD_TILE;  // 6399
    cd_stream_kernel<<<nblocks, CD_BLK>>>(sig, out, total_vec);
}

// round 11
// speedup vs baseline: 1.1546x; 1.1546x over previous
#include <cuda_runtime.h>
#include <cstdint>

// ChannelDropout, single fused kernel (resubmit of R6 — container infra failed,
// kernel never executed):
//   out[i] = sig[i] * scale[i / 750]
//   scale[ch] = kept(ch) / (eps + mean_j(||pos[ch]-mc[j]|| > 0.2))
//
// Per 2048-float4 tile: issue all 8 LDG.128/thread FIRST, then warps 0-3
// compute the <=4 channel scales this tile touches (hidden under the DRAM
// latency of the in-flight loads), sync, multiply, store.
//
// Shapes: B=64, C=273, T=3000.  T/4 = 750 float4 per channel.

#define CD_TVEC   750                  // float4 per channel
#define CD_NMC    100
#define CD_DROP   0.2f
#define CD_EPS    1e-8f
#define CD_VPT    8                    // float4 per thread
#define CD_BLK    256
#define CD_TILE   (CD_BLK * CD_VPT)    // 2048 float4 per block

__global__ __launch_bounds__(CD_BLK)
void cd_fused_kernel(const float4* __restrict__ sig,
                     const float*  __restrict__ pos,
                     const float*  __restrict__ center,
                     const float*  __restrict__ mc,
                     float4* __restrict__ out,
                     int total_vec, int BC)
{
    __shared__ float s_scale[4];

    const int tile0 = blockIdx.x * CD_TILE;
    const int base  = tile0 + threadIdx.x;
    const bool full = (tile0 + CD_TILE <= total_vec);

    // ---- 1) batch-issue the 8 sig loads (front-loaded MLP) ----
    float4 v[CD_VPT];
    if (full) {
#pragma unroll
        for (int j = 0; j < CD_VPT; j++)
            v[j] = __ldcs(&sig[base + j * CD_BLK]);
    } else {
#pragma unroll
        for (int j = 0; j < CD_VPT; j++)
            if (base + j * CD_BLK < total_vec)
                v[j] = __ldcs(&sig[base + j * CD_BLK]);
    }

    // ---- 2) warps 0-3: compute this tile's <=4 channel scales (hidden) ----
    const int wid      = threadIdx.x >> 5;
    const int lane     = threadIdx.x & 31;
    const int first_ch = tile0 / CD_TVEC;

    if (wid < 4) {
        const int ch = first_ch + wid;
        if (ch < BC) {
            const float px = pos[2 * ch + 0];
            const float py = pos[2 * ch + 1];

            // kept: distance from ban center (no FMA contraction -> match jax)
            const float dx = px - center[0];
            const float dy = py - center[1];
            const float d2 = __fadd_rn(__fmul_rn(dx, dx), __fmul_rn(dy, dy));
            const float kept = (sqrtf(d2) > CD_DROP) ? 1.0f : 0.0f;

            // Monte-Carlo: lanes parallel over the 100 trials
            int cnt = 0;
#pragma unroll
            for (int j = lane; j < CD_NMC; j += 32) {
                const float ddx = px - mc[2 * j + 0];
                const float ddy = py - mc[2 * j + 1];
                const float dd2 = __fadd_rn(__fmul_rn(ddx, ddx),
                                            __fmul_rn(ddy, ddy));
                cnt += (sqrtf(dd2) > CD_DROP) ? 1 : 0;
            }
#pragma unroll
            for (int off = 16; off > 0; off >>= 1)
                cnt += __shfl_xor_sync(0xffffffffu, cnt, off);

            if (lane == 0) {
                const float proba = (float)cnt / (float)CD_NMC;
                s_scale[wid] = kept / (CD_EPS + proba);
            }
        }
    }
    __syncthreads();

    // ---- 3) gather scale from smem broadcast, multiply, store ----
    if (full) {
        float s[CD_VPT];
#pragma unroll
        for (int j = 0; j < CD_VPT; j++)
            s[j] = s_scale[(unsigned)(base + j * CD_BLK) / CD_TVEC - first_ch];
#pragma unroll
        for (int j = 0; j < CD_VPT; j++) {
            float4 r;
            r.x = v[j].x * s[j];
            r.y = v[j].y * s[j];
            r.z = v[j].z * s[j];
            r.w = v[j].w * s[j];
            __stcs(&out[base + j * CD_BLK], r);
        }
    } else {
#pragma unroll
        for (int j = 0; j < CD_VPT; j++) {
            const int idx = base + j * CD_BLK;
            if (idx < total_vec) {
                const float s = s_scale[(unsigned)idx / CD_TVEC - first_ch];
                float4 r;
                r.x = v[j].x * s;
                r.y = v[j].y * s;
                r.z = v[j].z * s;
                r.w = v[j].w * s;
                __stcs(&out[idx], r);
            }
        }
    }
}

extern "C" void kernel_launch(void* const* d_in, const int* in_sizes, int n_in,
                              void* d_out, int out_size)
{
    const float4* sig    = (const float4*)d_in[0];   // brain_sig  (B,C,T) fp32
    const float*  pos    = (const float*) d_in[1];   // positions  (B,C,2)
    const float*  center = (const float*) d_in[2];   // center     (2,)
    const float*  mc     = (const float*) d_in[3];   // mc_centers (100,2)
    float4*       out    = (float4*)d_out;

    const int BC        = in_sizes[1] / 2;           // 17472
    const int total_vec = in_sizes[0] / 4;           // 13,104,000

    const int nblocks = (total_vec + CD_TILE - 1) / CD_TILE;  // 6399
    cd_fused_kernel<<<nblocks, CD_BLK>>>(sig, pos, center, mc, out,
                                         total_vec, BC);
}